// round 12
// baseline (speedup 1.0000x reference)
#include <cuda_runtime.h>
#include <math.h>
#include <stdint.h>

#define HIN     14
#define WIN     14
#define HO      12
#define WO      12
#define BATCH   4
#define FIN     32
#define DIN     8
#define FF      32
#define CCAP    288
#define DOUT    16
#define NPOS    (BATCH*HO*WO)   // 576
#define KDIM    (CCAP*DIN)      // 2304
#define NDIM    (FF*DOUT)       // 512

// ---------------- pass1 GEMM (tf32 mma) config -------------------------------
#define G_TM    64
#define G_TN    128
#define G_TK    32
#define G_TPB   256
#define G_KSPL  4
#define G_KC    (KDIM/G_KSPL)   // 576
#define G_NSTG  (G_KC/G_TK)     // 18
#define A_STR   36
#define B_STR   132
#define SMEM_A  (G_TM*A_STR)
#define SMEM_B  (G_TK*B_STR)
#define SMEM_G  ((SMEM_A + SMEM_B) * 2 * 4)

// ---------------- pass2 config ------------------------------------------------
#define TPB     256             // 8 warps, 4 pos/warp -> 32 pos/CTA
#define POSB2   32
#define NPB2    (NPOS/POSB2)    // 18
#define NCH2    8
#define CPC2    (CCAP/NCH2)     // 36 (18 duets)
// smem: 4 W stages (64KB) + o1 (64KB) + pr scratch (64KB)
#define SW_U64   (4 * 2048)
#define SO1_U64  (8 * POSB2 * 32)
#define SPR_U64  (8 * 8 * 4 * 32)
#define SMEM2_BYTES ((SW_U64 + SO1_U64 + SPR_U64) * 8)   // 192KB

typedef unsigned long long u64;

// ---------------- scratch (static device globals) ---------------------------
__device__ float2 g_Wtp[(size_t)CCAP*8*8*32];          // pass2 W: [c][i][p][f] pairs
__device__ float  g_Wb[(size_t)KDIM*NDIM];             // pass1 B: [k][(f,o)] tf32
__device__ float  g_C1[(size_t)G_KSPL*NPOS*NDIM];      // pass1 split-K partials
__device__ float2 g_out1p[(size_t)NPOS*FF*8];          // squash(iter1) fp32 pairs
__device__ float2 g_centp[(size_t)NCH2*NPOS*FF*8];     // pass2 partial centroids

__device__ __constant__ int c_koff[9] = {0, 256, 512, 3584, 3840, 4096, 7168, 7424, 7680};

// ---------------- helpers ----------------------------------------------------
__device__ __forceinline__ u64 pk(float lo, float hi) {
    u64 r; asm("mov.b64 %0,{%1,%2};" : "=l"(r) : "f"(lo), "f"(hi)); return r;
}
__device__ __forceinline__ void upk(u64 v, float& a, float& b) {
    asm("mov.b64 {%0,%1},%2;" : "=f"(a), "=f"(b) : "l"(v));
}
__device__ __forceinline__ u64 fma2(u64 a, u64 b, u64 c) {
    u64 d; asm("fma.rn.f32x2 %0,%1,%2,%3;" : "=l"(d) : "l"(a), "l"(b), "l"(c)); return d;
}
__device__ __forceinline__ uint32_t f2tf32(float v) {
    uint32_t r; asm("cvt.rna.tf32.f32 %0, %1;" : "=r"(r) : "f"(v)); return r;
}
__device__ __forceinline__ void mma_tf32(float c[4], const uint32_t a[4], const uint32_t b[2]) {
    asm volatile(
        "mma.sync.aligned.m16n8k8.row.col.f32.tf32.tf32.f32 "
        "{%0,%1,%2,%3}, {%4,%5,%6,%7}, {%8,%9}, {%0,%1,%2,%3};"
        : "+f"(c[0]), "+f"(c[1]), "+f"(c[2]), "+f"(c[3])
        : "r"(a[0]), "r"(a[1]), "r"(a[2]), "r"(a[3]), "r"(b[0]), "r"(b[1]));
}
__device__ __forceinline__ void cp16(uint32_t saddr, const void* gaddr) {
    asm volatile("cp.async.cg.shared.global [%0], [%1], 16;" :: "r"(saddr), "l"(gaddr));
}
template<int N>
__device__ __forceinline__ void wait_cp() {
    asm volatile("cp.async.wait_group %0;" :: "n"(N));
}
__device__ __forceinline__ void commit_cp() {
    asm volatile("cp.async.commit_group;");
}
__device__ __forceinline__ int pos_off(int pos) {
    int b = pos / (HO * WO);
    int r = pos % (HO * WO);
    int h = r / WO;
    int w = r % WO;
    return ((b * HIN + h) * WIN + w) * (FIN * DIN);
}

// ---------------- merged W prep: both layouts in one launch ------------------
__global__ void k_prep(const float* __restrict__ W) {
    int tid = blockIdx.x * blockDim.x + threadIdx.x;
    const int HALF = CCAP * 8 * 32;   // 73728
    if (tid < HALF) {
        // pass2 layout: Wtp[c][i][p][f] pairs (W[f,c,p,i], W[f,c,p+8,i])
        int f = tid & 31;
        int r = tid >> 5;
        int p = r & 7;
        int c = r >> 3;
        const float* row0 = W + (((size_t)f * CCAP + c) * DOUT + p) * DIN;
        const float* row8 = W + (((size_t)f * CCAP + c) * DOUT + p + 8) * DIN;
        float4 a0 = ((const float4*)row0)[0], a1 = ((const float4*)row0)[1];
        float4 b0 = ((const float4*)row8)[0], b1 = ((const float4*)row8)[1];
        float a[8] = {a0.x,a0.y,a0.z,a0.w,a1.x,a1.y,a1.z,a1.w};
        float b[8] = {b0.x,b0.y,b0.z,b0.w,b1.x,b1.y,b1.z,b1.w};
        #pragma unroll
        for (int i = 0; i < 8; ++i)
            g_Wtp[(((size_t)c * 8 + i) * 8 + p) * 32 + f] = make_float2(a[i], b[i]);
    } else if (tid < 2 * HALF) {
        // pass1 layout: Wb[(c*8+i)][(f*16+o)] = tf32(W[f][c][o][i])
        int t2 = tid - HALF;
        int f = t2 & 31;
        int i = (t2 >> 5) & 7;
        int c = t2 >> 8;
        const float* src = W + (((size_t)f * CCAP + c) * DOUT) * DIN + i;
        float* dst = g_Wb + ((size_t)c * 8 + i) * NDIM + f * 16;
        #pragma unroll
        for (int o = 0; o < 16; ++o)
            dst[o] = __uint_as_float(f2tf32(src[o * DIN]));
    }
}

// ---------------- pass 1: tf32 MMA GEMM, split-K (unchanged R11) -------------
__global__ void __launch_bounds__(G_TPB, 1) k_pass1mma(const float* __restrict__ x) {
    extern __shared__ float sm[];
    float* sA = sm;
    float* sB = sm + 2 * SMEM_A;
    __shared__ int sPos[G_TM];

    int tid   = threadIdx.x;
    int lane  = tid & 31;
    int warp  = tid >> 5;
    int wm    = warp >> 2;
    int wn    = warp & 3;
    int mtile = blockIdx.x;
    int ntile = blockIdx.y;
    int chunk = blockIdx.z;
    int cq0   = chunk * (G_KC / 8);

    if (tid < G_TM) sPos[tid] = pos_off(mtile * G_TM + tid);
    __syncthreads();

    float acc[2][4][4];
    #pragma unroll
    for (int mt = 0; mt < 2; ++mt)
        #pragma unroll
        for (int nt = 0; nt < 4; ++nt)
            #pragma unroll
            for (int q = 0; q < 4; ++q) acc[mt][nt][q] = 0.f;

    auto load_stage = [&](int s, int buf) {
        int cq  = cq0 + s * 4;
        int aoff = c_koff[cq >> 5] + (cq & 31) * DIN;
        uint32_t sa = (uint32_t)__cvta_generic_to_shared(sA + buf * SMEM_A);
        #pragma unroll
        for (int j = 0; j < 2; ++j) {
            int idx = tid + j * G_TPB;
            int row = idx >> 3;
            int c16 = idx & 7;
            cp16(sa + (row * A_STR + c16 * 4) * 4, x + sPos[row] + aoff + c16 * 4);
        }
        const float* gB = g_Wb + ((size_t)chunk * G_KC + s * G_TK) * NDIM + ntile * G_TN;
        uint32_t sb = (uint32_t)__cvta_generic_to_shared(sB + buf * SMEM_B);
        #pragma unroll
        for (int j = 0; j < 4; ++j) {
            int idx = tid + j * G_TPB;
            int k   = idx >> 5;
            int c16 = idx & 31;
            cp16(sb + (k * B_STR + c16 * 4) * 4, gB + (size_t)k * NDIM + c16 * 4);
        }
        commit_cp();
    };

    load_stage(0, 0);
    load_stage(1, 1);

    for (int s = 0; s < G_NSTG; ++s) {
        if (s + 1 < G_NSTG) wait_cp<1>(); else wait_cp<0>();
        __syncthreads();
        int buf = s & 1;
        const float* A = sA + buf * SMEM_A;
        const float* B = sB + buf * SMEM_B;

        #pragma unroll
        for (int k8 = 0; k8 < 4; ++k8) {
            int k0 = k8 * 8;
            uint32_t af[2][4];
            #pragma unroll
            for (int mt = 0; mt < 2; ++mt) {
                int row = wm * 32 + mt * 16 + (lane >> 2);
                int kk  = k0 + (lane & 3);
                af[mt][0] = f2tf32(A[row * A_STR + kk]);
                af[mt][1] = f2tf32(A[(row + 8) * A_STR + kk]);
                af[mt][2] = f2tf32(A[row * A_STR + kk + 4]);
                af[mt][3] = f2tf32(A[(row + 8) * A_STR + kk + 4]);
            }
            uint32_t bf[4][2];
            #pragma unroll
            for (int nt = 0; nt < 4; ++nt) {
                int col = wn * 32 + nt * 8 + (lane >> 2);
                int kk  = k0 + (lane & 3);
                bf[nt][0] = __float_as_uint(B[kk * B_STR + col]);
                bf[nt][1] = __float_as_uint(B[(kk + 4) * B_STR + col]);
            }
            #pragma unroll
            for (int mt = 0; mt < 2; ++mt)
                #pragma unroll
                for (int nt = 0; nt < 4; ++nt)
                    mma_tf32(acc[mt][nt], af[mt], bf[nt]);
        }

        __syncthreads();
        if (s + 2 < G_NSTG) load_stage(s + 2, buf);
    }

    #pragma unroll
    for (int mt = 0; mt < 2; ++mt) {
        int row = mtile * G_TM + wm * 32 + mt * 16 + (lane >> 2);
        #pragma unroll
        for (int nt = 0; nt < 4; ++nt) {
            int col = ntile * G_TN + wn * 32 + nt * 8 + (lane & 3) * 2;
            float* d0 = g_C1 + ((size_t)chunk * NPOS + row) * NDIM + col;
            float* d1 = g_C1 + ((size_t)chunk * NPOS + row + 8) * NDIM + col;
            d0[0] = acc[mt][nt][0]; d0[1] = acc[mt][nt][1];
            d1[0] = acc[mt][nt][2]; d1[1] = acc[mt][nt][3];
        }
    }
}

// ---------------- squash 1: reduce split-K, squash, pack pairs ---------------
__global__ void k_squash1() {
    int t = blockIdx.x * blockDim.x + threadIdx.x;   // (pos,f)
    if (t >= NPOS * FF) return;
    int pos = t >> 5;
    int f   = t & 31;
    float s[16];
    #pragma unroll
    for (int o = 0; o < 16; ++o) s[o] = 0.f;
    #pragma unroll
    for (int ch = 0; ch < G_KSPL; ++ch) {
        const float4* p = (const float4*)(g_C1 + ((size_t)ch * NPOS + pos) * NDIM + f * 16);
        #pragma unroll
        for (int q = 0; q < 4; ++q) {
            float4 v = p[q];
            s[q*4] += v.x; s[q*4+1] += v.y; s[q*4+2] += v.z; s[q*4+3] += v.w;
        }
    }
    float sn = 0.f;
    #pragma unroll
    for (int o = 0; o < 16; ++o) { s[o] *= (1.f / 32.f); sn += s[o] * s[o]; }
    float sc = (sn / (1.f + sn)) / sqrtf(sn + 1e-7f);
    float2* d = g_out1p + (size_t)t * 8;
    #pragma unroll
    for (int p = 0; p < 8; ++p) d[p] = make_float2(s[p] * sc, s[p + 8] * sc);
}

// ---------------- pass2 stage copy (16KB W tile) ------------------------------
__device__ __forceinline__ void stage_copy(u64* sdst, const float2* gsrc, int tid) {
    uint32_t s = (uint32_t)__cvta_generic_to_shared(sdst);
    const char* g = (const char*)gsrc;
    #pragma unroll
    for (int k = 0; k < 4; ++k) {
        int idx = tid + k * TPB;
        cp16(s + idx * 16, g + (size_t)idx * 16);
    }
    commit_cp();
}

// ---------------- pass 2: fused routing, pr staged through smem --------------
// p-outer pred loop keeps only t[4] live; pr stored in per-warp smem between
// agreement and centroid phases; o1 in smem. No register spills.
__global__ void __launch_bounds__(TPB, 1) k_pass2(const float* __restrict__ x) {
    extern __shared__ u64 smem[];
    u64* sW  = smem;                       // 4 x 2048 (64KB), 2 duets in flight
    u64* sO1 = smem + SW_U64;              // [p(8)][pos(32)][f(32)] (64KB)
    u64* sPr = smem + SW_U64 + SO1_U64;    // [warp(8)][p(8)][q(4)][f(32)] (64KB)

    int tid  = threadIdx.x;
    int lane = tid & 31;
    int w    = tid >> 5;
    int posb = blockIdx.x * POSB2;
    int wpos = w * 4;
    int pos0 = posb + wpos;
    int cch  = blockIdx.y;
    int cbeg = cch * CPC2;
    const int NT = CPC2 / 2;   // 18 duets

    const float* xb[4];
    #pragma unroll
    for (int q = 0; q < 4; ++q) xb[q] = x + pos_off(pos0 + q);

    // one-time: o1 (fp32 pairs) -> smem transposed to [p][pos][f]
    for (int idx = tid; idx < SO1_U64; idx += TPB) {
        int f    = idx & 31;
        int posl = (idx >> 5) & (POSB2 - 1);
        int p    = idx >> 10;
        sO1[(p * POSB2 + posl) * 32 + f] =
            ((const u64*)g_out1p)[(((size_t)(posb + posl) * FF) + f) * 8 + p];
    }

    u64* myPr = sPr + w * (8 * 4 * 32);

    u64 ce[4][8];
    #pragma unroll
    for (int q = 0; q < 4; ++q)
        #pragma unroll
        for (int p = 0; p < 8; ++p) ce[q][p] = 0ULL;

    // prologue: 2 duets (4 c's)
    #pragma unroll
    for (int j = 0; j < 4; ++j)
        stage_copy(sW + (size_t)j * 2048, g_Wtp + (size_t)(cbeg + j) * 2048, tid);

    for (int t = 0; t < NT; ++t) {
        if (t + 1 < NT) wait_cp<2>(); else wait_cp<0>();
        __syncthreads();
        int sset = (t & 1) * 2;
        int dbeg = cbeg + t * 2;

        #pragma unroll
        for (int k = 0; k < 2; ++k) {
            int j = (w + k) & 1;          // rotated duet order per warp
            int c = dbeg + j;
            int off = c_koff[c >> 5] + (c & 31) * DIN;

            u64 xd[4][8];
            #pragma unroll
            for (int q = 0; q < 4; ++q) {
                float4 v0 = ((const float4*)(xb[q] + off))[0];
                float4 v1 = ((const float4*)(xb[q] + off))[1];
                xd[q][0]=pk(v0.x,v0.x); xd[q][1]=pk(v0.y,v0.y);
                xd[q][2]=pk(v0.z,v0.z); xd[q][3]=pk(v0.w,v0.w);
                xd[q][4]=pk(v1.x,v1.x); xd[q][5]=pk(v1.y,v1.y);
                xd[q][6]=pk(v1.z,v1.z); xd[q][7]=pk(v1.w,v1.w);
            }

            const u64* wb = sW + (size_t)(sset + j) * 2048;
            u64 ag[4] = {0ULL, 0ULL, 0ULL, 0ULL};

            #pragma unroll
            for (int p = 0; p < 8; ++p) {
                u64 t0 = 0ULL, t1 = 0ULL, t2 = 0ULL, t3 = 0ULL;
                #pragma unroll
                for (int i = 0; i < 8; ++i) {
                    u64 wv = wb[(i * 8 + p) * 32 + lane];
                    t0 = fma2(wv, xd[0][i], t0);
                    t1 = fma2(wv, xd[1][i], t1);
                    t2 = fma2(wv, xd[2][i], t2);
                    t3 = fma2(wv, xd[3][i], t3);
                }
                // agreement contribution + stash pred pair
                ag[0] = fma2(t0, sO1[(p * POSB2 + wpos + 0) * 32 + lane], ag[0]);
                ag[1] = fma2(t1, sO1[(p * POSB2 + wpos + 1) * 32 + lane], ag[1]);
                ag[2] = fma2(t2, sO1[(p * POSB2 + wpos + 2) * 32 + lane], ag[2]);
                ag[3] = fma2(t3, sO1[(p * POSB2 + wpos + 3) * 32 + lane], ag[3]);
                myPr[(p * 4 + 0) * 32 + lane] = t0;
                myPr[(p * 4 + 1) * 32 + lane] = t1;
                myPr[(p * 4 + 2) * 32 + lane] = t2;
                myPr[(p * 4 + 3) * 32 + lane] = t3;
            }

            // softmax over f (lanes); no max-subtraction (|agreement| is O(1))
            float e[4];
            #pragma unroll
            for (int q = 0; q < 4; ++q) {
                float l, h;
                upk(ag[q], l, h);
                e[q] = __expf(l + h);
            }
            float s0 = e[0], s1 = e[1], s2 = e[2], s3 = e[3];
            #pragma unroll
            for (int d = 16; d > 0; d >>= 1) {
                s0 += __shfl_xor_sync(0xffffffffu, s0, d);
                s1 += __shfl_xor_sync(0xffffffffu, s1, d);
                s2 += __shfl_xor_sync(0xffffffffu, s2, d);
                s3 += __shfl_xor_sync(0xffffffffu, s3, d);
            }
            u64 cd0 = pk(__fdividef(e[0], s0), __fdividef(e[0], s0));
            u64 cd1 = pk(__fdividef(e[1], s1), __fdividef(e[1], s1));
            u64 cd2 = pk(__fdividef(e[2], s2), __fdividef(e[2], s2));
            u64 cd3 = pk(__fdividef(e[3], s3), __fdividef(e[3], s3));

            // centroid accumulate from stashed preds
            #pragma unroll
            for (int p = 0; p < 8; ++p) {
                ce[0][p] = fma2(myPr[(p * 4 + 0) * 32 + lane], cd0, ce[0][p]);
                ce[1][p] = fma2(myPr[(p * 4 + 1) * 32 + lane], cd1, ce[1][p]);
                ce[2][p] = fma2(myPr[(p * 4 + 2) * 32 + lane], cd2, ce[2][p]);
                ce[3][p] = fma2(myPr[(p * 4 + 3) * 32 + lane], cd3, ce[3][p]);
            }
        }

        __syncthreads();
        if (t + 2 < NT) {
            #pragma unroll
            for (int j = 0; j < 2; ++j)
                stage_copy(sW + (size_t)(sset + j) * 2048,
                           g_Wtp + (size_t)(cbeg + (t + 2) * 2 + j) * 2048, tid);
        }
    }

    #pragma unroll
    for (int q = 0; q < 4; ++q) {
        u64* d = (u64*)g_centp + (((size_t)cch * NPOS + pos0 + q) * FF + lane) * 8;
        #pragma unroll
        for (int p = 0; p < 8; ++p) d[p] = ce[q][p];
    }
}

// ---------------- squash 2: final output ------------------------------------
__global__ void k_squash2(float* __restrict__ out) {
    int t = blockIdx.x * blockDim.x + threadIdx.x;   // (pos,f)
    if (t >= NPOS * FF) return;
    float sx[8], sy[8];
    #pragma unroll
    for (int p = 0; p < 8; ++p) { sx[p] = 0.f; sy[p] = 0.f; }
    for (int ch = 0; ch < NCH2; ++ch) {
        const float2* s = g_centp + ((size_t)ch * NPOS * FF + t) * 8;
        #pragma unroll
        for (int p = 0; p < 8; ++p) { float2 v = s[p]; sx[p] += v.x; sy[p] += v.y; }
    }
    float sn = 0.f;
    #pragma unroll
    for (int p = 0; p < 8; ++p) sn += sx[p] * sx[p] + sy[p] * sy[p];
    float sc = (sn / (1.f + sn)) / sqrtf(sn + 1e-7f);
    float* d = out + (size_t)t * DOUT;
    #pragma unroll
    for (int p = 0; p < 8; ++p) { d[p] = sx[p] * sc; d[p + 8] = sy[p] * sc; }
}

// -----------------------------------------------------------------------------
extern "C" void kernel_launch(void* const* d_in, const int* in_sizes, int n_in,
                              void* d_out, int out_size) {
    const float* x = (const float*)d_in[0];
    const float* W = (const float*)d_in[1];
    if (n_in >= 2 && in_sizes[0] == (int)((size_t)FF * CCAP * DOUT * DIN)) {
        const float* t = x; x = W; W = t;
    }
    float* out = (float*)d_out;

    cudaFuncSetAttribute(k_pass1mma, cudaFuncAttributeMaxDynamicSharedMemorySize, SMEM_G);
    cudaFuncSetAttribute(k_pass2, cudaFuncAttributeMaxDynamicSharedMemorySize, SMEM2_BYTES);

    k_prep<<<(2 * CCAP * 8 * 32 + 255) / 256, 256>>>(W);
    k_pass1mma<<<dim3(NPOS / G_TM, NDIM / G_TN, G_KSPL), G_TPB, SMEM_G>>>(x);
    k_squash1<<<(NPOS * FF + 127) / 128, 128>>>();
    k_pass2<<<dim3(NPB2, NCH2), TPB, SMEM2_BYTES>>>(x);
    k_squash2<<<(NPOS * FF + 255) / 256, 256>>>(out);
}

// round 13
// speedup vs baseline: 1.0258x; 1.0258x over previous
#include <cuda_runtime.h>
#include <math.h>
#include <stdint.h>

#define HIN     14
#define WIN     14
#define HO      12
#define WO      12
#define BATCH   4
#define FIN     32
#define DIN     8
#define FF      32
#define CCAP    288
#define DOUT    16
#define NPOS    (BATCH*HO*WO)   // 576
#define KDIM    (CCAP*DIN)      // 2304
#define NDIM    (FF*DOUT)       // 512

// ---------------- pass1 GEMM (tf32 mma) config -------------------------------
#define G_TM    64
#define G_TN    128
#define G_TK    32
#define G_TPB   256
#define G_KSPL  4
#define G_KC    (KDIM/G_KSPL)   // 576
#define G_NSTG  (G_KC/G_TK)     // 18
#define A_STR   36
#define B_STR   132
#define SMEM_A  (G_TM*A_STR)
#define SMEM_B  (G_TK*B_STR)
#define SMEM_G  ((SMEM_A + SMEM_B) * 2 * 4)

// ---------------- pass2 config: 12 warps, 3 pos/warp --------------------------
#define TPB2    384
#define POSB2   36              // 12 warps * 3
#define NPB2    (NPOS/POSB2)    // 16
#define NCH2    9
#define CPC2    (CCAP/NCH2)     // 32 (8 quartets)
#define SW_U64   (8 * 2048)               // 8 W stages = 128KB
#define SO1_U64  (8 * POSB2 * 32)         // o1 [p][pos][f] = 72KB
#define SMEM2_BYTES ((SW_U64 + SO1_U64) * 8)   // 200KB

typedef unsigned long long u64;

// ---------------- scratch (static device globals) ---------------------------
__device__ float2 g_Wtp[(size_t)CCAP*8*8*32];          // pass2 W: [c][i][p][f] pairs
__device__ float  g_Wb[(size_t)KDIM*NDIM];             // pass1 B: [k][(f,o)] tf32
__device__ float  g_C1[(size_t)G_KSPL*NPOS*NDIM];      // pass1 split-K partials
__device__ float2 g_out1p[(size_t)NPOS*FF*8];          // squash(iter1) fp32 pairs
__device__ float2 g_centp[(size_t)NCH2*NPOS*FF*8];     // pass2 partial centroids

__device__ __constant__ int c_koff[9] = {0, 256, 512, 3584, 3840, 4096, 7168, 7424, 7680};

// ---------------- helpers ----------------------------------------------------
__device__ __forceinline__ u64 pk(float lo, float hi) {
    u64 r; asm("mov.b64 %0,{%1,%2};" : "=l"(r) : "f"(lo), "f"(hi)); return r;
}
__device__ __forceinline__ void upk(u64 v, float& a, float& b) {
    asm("mov.b64 {%0,%1},%2;" : "=f"(a), "=f"(b) : "l"(v));
}
__device__ __forceinline__ u64 fma2(u64 a, u64 b, u64 c) {
    u64 d; asm("fma.rn.f32x2 %0,%1,%2,%3;" : "=l"(d) : "l"(a), "l"(b), "l"(c)); return d;
}
__device__ __forceinline__ uint32_t f2tf32(float v) {
    uint32_t r; asm("cvt.rna.tf32.f32 %0, %1;" : "=r"(r) : "f"(v)); return r;
}
__device__ __forceinline__ void mma_tf32(float c[4], const uint32_t a[4], const uint32_t b[2]) {
    asm volatile(
        "mma.sync.aligned.m16n8k8.row.col.f32.tf32.tf32.f32 "
        "{%0,%1,%2,%3}, {%4,%5,%6,%7}, {%8,%9}, {%0,%1,%2,%3};"
        : "+f"(c[0]), "+f"(c[1]), "+f"(c[2]), "+f"(c[3])
        : "r"(a[0]), "r"(a[1]), "r"(a[2]), "r"(a[3]), "r"(b[0]), "r"(b[1]));
}
__device__ __forceinline__ void cp16(uint32_t saddr, const void* gaddr) {
    asm volatile("cp.async.cg.shared.global [%0], [%1], 16;" :: "r"(saddr), "l"(gaddr));
}
template<int N>
__device__ __forceinline__ void wait_cp() {
    asm volatile("cp.async.wait_group %0;" :: "n"(N));
}
__device__ __forceinline__ void commit_cp() {
    asm volatile("cp.async.commit_group;");
}
__device__ __forceinline__ int pos_off(int pos) {
    int b = pos / (HO * WO);
    int r = pos % (HO * WO);
    int h = r / WO;
    int w = r % WO;
    return ((b * HIN + h) * WIN + w) * (FIN * DIN);
}

// ---------------- merged W prep -----------------------------------------------
__global__ void k_prep(const float* __restrict__ W) {
    int tid = blockIdx.x * blockDim.x + threadIdx.x;
    const int HALF = CCAP * 8 * 32;
    if (tid < HALF) {
        int f = tid & 31;
        int r = tid >> 5;
        int p = r & 7;
        int c = r >> 3;
        const float* row0 = W + (((size_t)f * CCAP + c) * DOUT + p) * DIN;
        const float* row8 = W + (((size_t)f * CCAP + c) * DOUT + p + 8) * DIN;
        float4 a0 = ((const float4*)row0)[0], a1 = ((const float4*)row0)[1];
        float4 b0 = ((const float4*)row8)[0], b1 = ((const float4*)row8)[1];
        float a[8] = {a0.x,a0.y,a0.z,a0.w,a1.x,a1.y,a1.z,a1.w};
        float b[8] = {b0.x,b0.y,b0.z,b0.w,b1.x,b1.y,b1.z,b1.w};
        #pragma unroll
        for (int i = 0; i < 8; ++i)
            g_Wtp[(((size_t)c * 8 + i) * 8 + p) * 32 + f] = make_float2(a[i], b[i]);
    } else if (tid < 2 * HALF) {
        int t2 = tid - HALF;
        int f = t2 & 31;
        int i = (t2 >> 5) & 7;
        int c = t2 >> 8;
        const float* src = W + (((size_t)f * CCAP + c) * DOUT) * DIN + i;
        float* dst = g_Wb + ((size_t)c * 8 + i) * NDIM + f * 16;
        #pragma unroll
        for (int o = 0; o < 16; ++o)
            dst[o] = __uint_as_float(f2tf32(src[o * DIN]));
    }
}

// ---------------- pass 1: tf32 MMA GEMM, split-K (R11, unchanged) ------------
__global__ void __launch_bounds__(G_TPB, 1) k_pass1mma(const float* __restrict__ x) {
    extern __shared__ float sm[];
    float* sA = sm;
    float* sB = sm + 2 * SMEM_A;
    __shared__ int sPos[G_TM];

    int tid   = threadIdx.x;
    int lane  = tid & 31;
    int warp  = tid >> 5;
    int wm    = warp >> 2;
    int wn    = warp & 3;
    int mtile = blockIdx.x;
    int ntile = blockIdx.y;
    int chunk = blockIdx.z;
    int cq0   = chunk * (G_KC / 8);

    if (tid < G_TM) sPos[tid] = pos_off(mtile * G_TM + tid);
    __syncthreads();

    float acc[2][4][4];
    #pragma unroll
    for (int mt = 0; mt < 2; ++mt)
        #pragma unroll
        for (int nt = 0; nt < 4; ++nt)
            #pragma unroll
            for (int q = 0; q < 4; ++q) acc[mt][nt][q] = 0.f;

    auto load_stage = [&](int s, int buf) {
        int cq  = cq0 + s * 4;
        int aoff = c_koff[cq >> 5] + (cq & 31) * DIN;
        uint32_t sa = (uint32_t)__cvta_generic_to_shared(sA + buf * SMEM_A);
        #pragma unroll
        for (int j = 0; j < 2; ++j) {
            int idx = tid + j * G_TPB;
            int row = idx >> 3;
            int c16 = idx & 7;
            cp16(sa + (row * A_STR + c16 * 4) * 4, x + sPos[row] + aoff + c16 * 4);
        }
        const float* gB = g_Wb + ((size_t)chunk * G_KC + s * G_TK) * NDIM + ntile * G_TN;
        uint32_t sb = (uint32_t)__cvta_generic_to_shared(sB + buf * SMEM_B);
        #pragma unroll
        for (int j = 0; j < 4; ++j) {
            int idx = tid + j * G_TPB;
            int k   = idx >> 5;
            int c16 = idx & 31;
            cp16(sb + (k * B_STR + c16 * 4) * 4, gB + (size_t)k * NDIM + c16 * 4);
        }
        commit_cp();
    };

    load_stage(0, 0);
    load_stage(1, 1);

    for (int s = 0; s < G_NSTG; ++s) {
        if (s + 1 < G_NSTG) wait_cp<1>(); else wait_cp<0>();
        __syncthreads();
        int buf = s & 1;
        const float* A = sA + buf * SMEM_A;
        const float* B = sB + buf * SMEM_B;

        #pragma unroll
        for (int k8 = 0; k8 < 4; ++k8) {
            int k0 = k8 * 8;
            uint32_t af[2][4];
            #pragma unroll
            for (int mt = 0; mt < 2; ++mt) {
                int row = wm * 32 + mt * 16 + (lane >> 2);
                int kk  = k0 + (lane & 3);
                af[mt][0] = f2tf32(A[row * A_STR + kk]);
                af[mt][1] = f2tf32(A[(row + 8) * A_STR + kk]);
                af[mt][2] = f2tf32(A[row * A_STR + kk + 4]);
                af[mt][3] = f2tf32(A[(row + 8) * A_STR + kk + 4]);
            }
            uint32_t bf[4][2];
            #pragma unroll
            for (int nt = 0; nt < 4; ++nt) {
                int col = wn * 32 + nt * 8 + (lane >> 2);
                int kk  = k0 + (lane & 3);
                bf[nt][0] = __float_as_uint(B[kk * B_STR + col]);
                bf[nt][1] = __float_as_uint(B[(kk + 4) * B_STR + col]);
            }
            #pragma unroll
            for (int mt = 0; mt < 2; ++mt)
                #pragma unroll
                for (int nt = 0; nt < 4; ++nt)
                    mma_tf32(acc[mt][nt], af[mt], bf[nt]);
        }

        __syncthreads();
        if (s + 2 < G_NSTG) load_stage(s + 2, buf);
    }

    #pragma unroll
    for (int mt = 0; mt < 2; ++mt) {
        int row = mtile * G_TM + wm * 32 + mt * 16 + (lane >> 2);
        #pragma unroll
        for (int nt = 0; nt < 4; ++nt) {
            int col = ntile * G_TN + wn * 32 + nt * 8 + (lane & 3) * 2;
            float* d0 = g_C1 + ((size_t)chunk * NPOS + row) * NDIM + col;
            float* d1 = g_C1 + ((size_t)chunk * NPOS + row + 8) * NDIM + col;
            d0[0] = acc[mt][nt][0]; d0[1] = acc[mt][nt][1];
            d1[0] = acc[mt][nt][2]; d1[1] = acc[mt][nt][3];
        }
    }
}

// ---------------- squash 1 -----------------------------------------------------
__global__ void k_squash1() {
    int t = blockIdx.x * blockDim.x + threadIdx.x;
    if (t >= NPOS * FF) return;
    int pos = t >> 5;
    int f   = t & 31;
    float s[16];
    #pragma unroll
    for (int o = 0; o < 16; ++o) s[o] = 0.f;
    #pragma unroll
    for (int ch = 0; ch < G_KSPL; ++ch) {
        const float4* p = (const float4*)(g_C1 + ((size_t)ch * NPOS + pos) * NDIM + f * 16);
        #pragma unroll
        for (int q = 0; q < 4; ++q) {
            float4 v = p[q];
            s[q*4] += v.x; s[q*4+1] += v.y; s[q*4+2] += v.z; s[q*4+3] += v.w;
        }
    }
    float sn = 0.f;
    #pragma unroll
    for (int o = 0; o < 16; ++o) { s[o] *= (1.f / 32.f); sn += s[o] * s[o]; }
    float sc = (sn / (1.f + sn)) / sqrtf(sn + 1e-7f);
    float2* d = g_out1p + (size_t)t * 8;
    #pragma unroll
    for (int p = 0; p < 8; ++p) d[p] = make_float2(s[p] * sc, s[p + 8] * sc);
}

// ---------------- pass2 stage copy (16KB W tile) -------------------------------
__device__ __forceinline__ void stage_copy2(u64* sdst, const float2* gsrc, int tid) {
    uint32_t s = (uint32_t)__cvta_generic_to_shared(sdst);
    const char* g = (const char*)gsrc;
    for (int k = tid; k < 1024; k += TPB2) cp16(s + k * 16, g + (size_t)k * 16);
    commit_cp();
}

// ---------------- pass 2: 12 warps, 3 pos/warp, o1 in smem, no spills --------
__global__ void __launch_bounds__(TPB2, 1) k_pass2(const float* __restrict__ x) {
    extern __shared__ u64 smem[];
    u64* sW  = smem;                 // 8 x 2048 u64 (128KB)
    u64* sO1 = smem + SW_U64;        // [p(8)][pos(36)][f(32)] (72KB)

    int tid  = threadIdx.x;
    int lane = tid & 31;
    int w    = tid >> 5;
    int posb = blockIdx.x * POSB2;
    int wpos = w * 3;
    int pos0 = posb + wpos;
    int cch  = blockIdx.y;
    int cbeg = cch * CPC2;
    const int NT = CPC2 / 4;   // 8 quartets

    const float* xb[3];
    #pragma unroll
    for (int q = 0; q < 3; ++q) xb[q] = x + pos_off(pos0 + q);

    // one-time: o1 (fp32 pairs) -> smem transposed to [p][pos][f]
    for (int idx = tid; idx < SO1_U64; idx += TPB2) {
        int f    = idx & 31;
        int r    = idx >> 5;
        int posl = r % POSB2;
        int p    = r / POSB2;
        sO1[(p * POSB2 + posl) * 32 + f] =
            ((const u64*)g_out1p)[(((size_t)(posb + posl) * FF) + f) * 8 + p];
    }

    u64 ce[3][8];
    #pragma unroll
    for (int q = 0; q < 3; ++q)
        #pragma unroll
        for (int p = 0; p < 8; ++p) ce[q][p] = 0ULL;

    #pragma unroll
    for (int j = 0; j < 4; ++j)
        stage_copy2(sW + (size_t)j * 2048, g_Wtp + (size_t)(cbeg + j) * 2048, tid);
    #pragma unroll
    for (int j = 0; j < 4; ++j)
        stage_copy2(sW + (size_t)(4 + j) * 2048, g_Wtp + (size_t)(cbeg + 4 + j) * 2048, tid);

    for (int t = 0; t < NT; ++t) {
        if (t + 1 < NT) wait_cp<4>(); else wait_cp<0>();
        __syncthreads();
        int sset = (t & 1) * 4;
        int qbeg = cbeg + t * 4;

        #pragma unroll
        for (int k = 0; k < 4; ++k) {
            int j = (w + k) & 3;          // rotated order per warp -> phase mixing
            int c = qbeg + j;
            int off = c_koff[c >> 5] + (c & 31) * DIN;
            float xs[3][8];
            #pragma unroll
            for (int q = 0; q < 3; ++q) {
                float4 v0 = ((const float4*)(xb[q] + off))[0];
                float4 v1 = ((const float4*)(xb[q] + off))[1];
                xs[q][0]=v0.x; xs[q][1]=v0.y; xs[q][2]=v0.z; xs[q][3]=v0.w;
                xs[q][4]=v1.x; xs[q][5]=v1.y; xs[q][6]=v1.z; xs[q][7]=v1.w;
            }

            u64 pr[3][8];
            #pragma unroll
            for (int q = 0; q < 3; ++q)
                #pragma unroll
                for (int p = 0; p < 8; ++p) pr[q][p] = 0ULL;

            const u64* wb = sW + (size_t)(sset + j) * 2048;
            #pragma unroll
            for (int i = 0; i < 8; ++i) {
                u64 xd0 = pk(xs[0][i], xs[0][i]);
                u64 xd1 = pk(xs[1][i], xs[1][i]);
                u64 xd2 = pk(xs[2][i], xs[2][i]);
                #pragma unroll
                for (int p = 0; p < 8; ++p) {
                    u64 wv = wb[(i * 8 + p) * 32 + lane];
                    pr[0][p] = fma2(wv, xd0, pr[0][p]);
                    pr[1][p] = fma2(wv, xd1, pr[1][p]);
                    pr[2][p] = fma2(wv, xd2, pr[2][p]);
                }
            }

            // agreement dots with o1 from smem (conflict-free LDS.64, lane=f)
            float e[3];
            #pragma unroll
            for (int q = 0; q < 3; ++q) {
                u64 a = 0ULL;
                #pragma unroll
                for (int p = 0; p < 8; ++p)
                    a = fma2(pr[q][p], sO1[(p * POSB2 + wpos + q) * 32 + lane], a);
                float l, h;
                upk(a, l, h);
                e[q] = __expf(l + h);   // no max-subtraction: |agreement| is O(1)
            }

            float s0 = e[0], s1 = e[1], s2 = e[2];
            #pragma unroll
            for (int d = 16; d > 0; d >>= 1) {
                s0 += __shfl_xor_sync(0xffffffffu, s0, d);
                s1 += __shfl_xor_sync(0xffffffffu, s1, d);
                s2 += __shfl_xor_sync(0xffffffffu, s2, d);
            }
            float c0 = __fdividef(e[0], s0);
            float c1 = __fdividef(e[1], s1);
            float c2 = __fdividef(e[2], s2);
            u64 cd0 = pk(c0, c0);
            u64 cd1 = pk(c1, c1);
            u64 cd2 = pk(c2, c2);

            #pragma unroll
            for (int p = 0; p < 8; ++p) {
                ce[0][p] = fma2(pr[0][p], cd0, ce[0][p]);
                ce[1][p] = fma2(pr[1][p], cd1, ce[1][p]);
                ce[2][p] = fma2(pr[2][p], cd2, ce[2][p]);
            }
        }

        __syncthreads();
        if (t + 2 < NT) {
            #pragma unroll
            for (int j = 0; j < 4; ++j)
                stage_copy2(sW + (size_t)(sset + j) * 2048,
                            g_Wtp + (size_t)(cbeg + (t + 2) * 4 + j) * 2048, tid);
        }
    }

    #pragma unroll
    for (int q = 0; q < 3; ++q) {
        u64* d = (u64*)g_centp + (((size_t)cch * NPOS + pos0 + q) * FF + lane) * 8;
        #pragma unroll
        for (int p = 0; p < 8; ++p) d[p] = ce[q][p];
    }
}

// ---------------- squash 2: final output ------------------------------------
__global__ void k_squash2(float* __restrict__ out) {
    int t = blockIdx.x * blockDim.x + threadIdx.x;
    if (t >= NPOS * FF) return;
    float sx[8], sy[8];
    #pragma unroll
    for (int p = 0; p < 8; ++p) { sx[p] = 0.f; sy[p] = 0.f; }
    for (int ch = 0; ch < NCH2; ++ch) {
        const float2* s = g_centp + ((size_t)ch * NPOS * FF + t) * 8;
        #pragma unroll
        for (int p = 0; p < 8; ++p) { float2 v = s[p]; sx[p] += v.x; sy[p] += v.y; }
    }
    float sn = 0.f;
    #pragma unroll
    for (int p = 0; p < 8; ++p) sn += sx[p] * sx[p] + sy[p] * sy[p];
    float sc = (sn / (1.f + sn)) / sqrtf(sn + 1e-7f);
    float* d = out + (size_t)t * DOUT;
    #pragma unroll
    for (int p = 0; p < 8; ++p) { d[p] = sx[p] * sc; d[p + 8] = sy[p] * sc; }
}

// -----------------------------------------------------------------------------
extern "C" void kernel_launch(void* const* d_in, const int* in_sizes, int n_in,
                              void* d_out, int out_size) {
    const float* x = (const float*)d_in[0];
    const float* W = (const float*)d_in[1];
    if (n_in >= 2 && in_sizes[0] == (int)((size_t)FF * CCAP * DOUT * DIN)) {
        const float* t = x; x = W; W = t;
    }
    float* out = (float*)d_out;

    cudaFuncSetAttribute(k_pass1mma, cudaFuncAttributeMaxDynamicSharedMemorySize, SMEM_G);
    cudaFuncSetAttribute(k_pass2, cudaFuncAttributeMaxDynamicSharedMemorySize, SMEM2_BYTES);

    k_prep<<<(2 * CCAP * 8 * 32 + 255) / 256, 256>>>(W);
    k_pass1mma<<<dim3(NPOS / G_TM, NDIM / G_TN, G_KSPL), G_TPB, SMEM_G>>>(x);
    k_squash1<<<(NPOS * FF + 127) / 128, 128>>>();
    k_pass2<<<dim3(NPB2, NCH2), TPB2, SMEM2_BYTES>>>(x);
    k_squash2<<<(NPOS * FF + 255) / 256, 256>>>(out);
}

// round 14
// speedup vs baseline: 1.2771x; 1.2450x over previous
#include <cuda_runtime.h>
#include <math.h>
#include <stdint.h>

#define HIN     14
#define WIN     14
#define HO      12
#define WO      12
#define BATCH   4
#define FIN     32
#define DIN     8
#define FF      32
#define CCAP    288
#define DOUT    16
#define NPOS    (BATCH*HO*WO)   // 576
#define KDIM    (CCAP*DIN)      // 2304
#define NDIM    (FF*DOUT)       // 512

// ---------------- pass1 GEMM (tf32 mma) config -------------------------------
#define G_TM    64
#define G_TN    128
#define G_TK    32
#define G_TPB   256
#define G_KSPL  4
#define G_KC    (KDIM/G_KSPL)   // 576
#define G_NSTG  (G_KC/G_TK)     // 18
#define A_STR   36
#define B_STR   132
#define SMEM_A  (G_TM*A_STR)
#define SMEM_B  (G_TK*B_STR)
#define SMEM_G  ((SMEM_A + SMEM_B) * 3 * 4)   // 3-stage pipeline

// ---------------- pass2 config (R7 champion) ----------------------------------
#define TPB     256
#define POSB2   32
#define NPB2    (NPOS/POSB2)    // 18
#define NCH2    8
#define CPC2    (CCAP/NCH2)     // 36 (9 quartets)
#define SMEM_BYTES (8 * 2048 * 8)   // 8 stages x 16KB = 128KB

typedef unsigned long long u64;

// ---------------- scratch (static device globals) ---------------------------
__device__ float2 g_Wtp[(size_t)CCAP*8*8*32];          // pass2 W: [c][i][p][f] pairs
__device__ float  g_Wb[(size_t)KDIM*NDIM];             // pass1 B: [k][(f,o)] tf32
__device__ float  g_C1[(size_t)G_KSPL*NPOS*NDIM];      // pass1 split-K partials
__device__ float2 g_out1p[(size_t)NPOS*FF*8];          // squash(iter1) fp32 pairs
__device__ float2 g_centp[(size_t)NCH2*NPOS*FF*8];     // pass2 partial centroids

__device__ __constant__ int c_koff[9] = {0, 256, 512, 3584, 3840, 4096, 7168, 7424, 7680};

// ---------------- helpers ----------------------------------------------------
__device__ __forceinline__ u64 pk(float lo, float hi) {
    u64 r; asm("mov.b64 %0,{%1,%2};" : "=l"(r) : "f"(lo), "f"(hi)); return r;
}
__device__ __forceinline__ void upk(u64 v, float& a, float& b) {
    asm("mov.b64 {%0,%1},%2;" : "=f"(a), "=f"(b) : "l"(v));
}
__device__ __forceinline__ u64 fma2(u64 a, u64 b, u64 c) {
    u64 d; asm("fma.rn.f32x2 %0,%1,%2,%3;" : "=l"(d) : "l"(a), "l"(b), "l"(c)); return d;
}
__device__ __forceinline__ uint32_t f2tf32(float v) {
    uint32_t r; asm("cvt.rna.tf32.f32 %0, %1;" : "=r"(r) : "f"(v)); return r;
}
__device__ __forceinline__ void mma_tf32(float c[4], const uint32_t a[4], const uint32_t b[2]) {
    asm volatile(
        "mma.sync.aligned.m16n8k8.row.col.f32.tf32.tf32.f32 "
        "{%0,%1,%2,%3}, {%4,%5,%6,%7}, {%8,%9}, {%0,%1,%2,%3};"
        : "+f"(c[0]), "+f"(c[1]), "+f"(c[2]), "+f"(c[3])
        : "r"(a[0]), "r"(a[1]), "r"(a[2]), "r"(a[3]), "r"(b[0]), "r"(b[1]));
}
__device__ __forceinline__ void cp16(uint32_t saddr, const void* gaddr) {
    asm volatile("cp.async.cg.shared.global [%0], [%1], 16;" :: "r"(saddr), "l"(gaddr));
}
template<int N>
__device__ __forceinline__ void wait_cp() {
    asm volatile("cp.async.wait_group %0;" :: "n"(N));
}
__device__ __forceinline__ void commit_cp() {
    asm volatile("cp.async.commit_group;");
}
__device__ __forceinline__ int pos_off(int pos) {
    int b = pos / (HO * WO);
    int r = pos % (HO * WO);
    int h = r / WO;
    int w = r % WO;
    return ((b * HIN + h) * WIN + w) * (FIN * DIN);
}

// ---------------- W prep: block-per-c, coalesced both ways --------------------
__global__ void k_prep(const float* __restrict__ W) {
    __shared__ float sWc[32][128];   // [f][o*8+i] slice for this c (16KB)
    int c   = blockIdx.x;
    int tid = threadIdx.x;
    // coalesced load: each f row = 128 contiguous floats
    for (int idx = tid; idx < 32 * 32; idx += 256) {
        int f = idx >> 5, j = idx & 31;
        ((float4*)&sWc[f][0])[j] =
            ((const float4*)(W + ((size_t)f * CCAP + c) * 128))[j];
    }
    __syncthreads();
    // pass2 layout: Wtp[c][i][p][f] = (W[f,c,p,i], W[f,c,p+8,i]); coalesced in f
    for (int idx = tid; idx < 2048; idx += 256) {
        int f = idx & 31, p = (idx >> 5) & 7, i = idx >> 8;
        g_Wtp[(((size_t)c * 8 + i) * 8 + p) * 32 + f] =
            make_float2(sWc[f][p * 8 + i], sWc[f][(p + 8) * 8 + i]);
    }
    // pass1 layout: Wb[(c*8+i)][f*16+o] = tf32; coalesced in n
    for (int idx = tid; idx < 4096; idx += 256) {
        int n = idx & 511, i = idx >> 9;
        int f = n >> 4, o = n & 15;
        g_Wb[((size_t)c * 8 + i) * NDIM + n] =
            __uint_as_float(f2tf32(sWc[f][o * 8 + i]));
    }
}

// ---------------- pass 1: tf32 MMA GEMM, split-K, 3-stage pipeline ------------
__global__ void __launch_bounds__(G_TPB, 1) k_pass1mma(const float* __restrict__ x) {
    extern __shared__ float sm[];
    float* sA = sm;                       // [3][SMEM_A]
    float* sB = sm + 3 * SMEM_A;          // [3][SMEM_B]
    __shared__ int sPos[G_TM];

    int tid   = threadIdx.x;
    int lane  = tid & 31;
    int warp  = tid >> 5;
    int wm    = warp >> 2;
    int wn    = warp & 3;
    int mtile = blockIdx.x;
    int ntile = blockIdx.y;
    int chunk = blockIdx.z;
    int cq0   = chunk * (G_KC / 8);

    if (tid < G_TM) sPos[tid] = pos_off(mtile * G_TM + tid);
    __syncthreads();

    float acc[2][4][4];
    #pragma unroll
    for (int mt = 0; mt < 2; ++mt)
        #pragma unroll
        for (int nt = 0; nt < 4; ++nt)
            #pragma unroll
            for (int q = 0; q < 4; ++q) acc[mt][nt][q] = 0.f;

    auto load_stage = [&](int s, int buf) {
        int cq  = cq0 + s * 4;
        int aoff = c_koff[cq >> 5] + (cq & 31) * DIN;
        uint32_t sa = (uint32_t)__cvta_generic_to_shared(sA + buf * SMEM_A);
        #pragma unroll
        for (int j = 0; j < 2; ++j) {
            int idx = tid + j * G_TPB;
            int row = idx >> 3;
            int c16 = idx & 7;
            cp16(sa + (row * A_STR + c16 * 4) * 4, x + sPos[row] + aoff + c16 * 4);
        }
        const float* gB = g_Wb + ((size_t)chunk * G_KC + s * G_TK) * NDIM + ntile * G_TN;
        uint32_t sb = (uint32_t)__cvta_generic_to_shared(sB + buf * SMEM_B);
        #pragma unroll
        for (int j = 0; j < 4; ++j) {
            int idx = tid + j * G_TPB;
            int k   = idx >> 5;
            int c16 = idx & 31;
            cp16(sb + (k * B_STR + c16 * 4) * 4, gB + (size_t)k * NDIM + c16 * 4);
        }
        commit_cp();
    };

    load_stage(0, 0);
    load_stage(1, 1);
    load_stage(2, 2);

    for (int s = 0; s < G_NSTG; ++s) {
        if (s + 3 <= G_NSTG) wait_cp<2>();
        else if (s + 2 == G_NSTG) wait_cp<1>();
        else wait_cp<0>();
        __syncthreads();
        int buf = s % 3;
        const float* A = sA + buf * SMEM_A;
        const float* B = sB + buf * SMEM_B;

        #pragma unroll
        for (int k8 = 0; k8 < 4; ++k8) {
            int k0 = k8 * 8;
            uint32_t af[2][4];
            #pragma unroll
            for (int mt = 0; mt < 2; ++mt) {
                int row = wm * 32 + mt * 16 + (lane >> 2);
                int kk  = k0 + (lane & 3);
                af[mt][0] = f2tf32(A[row * A_STR + kk]);
                af[mt][1] = f2tf32(A[(row + 8) * A_STR + kk]);
                af[mt][2] = f2tf32(A[row * A_STR + kk + 4]);
                af[mt][3] = f2tf32(A[(row + 8) * A_STR + kk + 4]);
            }
            uint32_t bf[4][2];
            #pragma unroll
            for (int nt = 0; nt < 4; ++nt) {
                int col = wn * 32 + nt * 8 + (lane >> 2);
                int kk  = k0 + (lane & 3);
                bf[nt][0] = __float_as_uint(B[kk * B_STR + col]);
                bf[nt][1] = __float_as_uint(B[(kk + 4) * B_STR + col]);
            }
            #pragma unroll
            for (int mt = 0; mt < 2; ++mt)
                #pragma unroll
                for (int nt = 0; nt < 4; ++nt)
                    mma_tf32(acc[mt][nt], af[mt], bf[nt]);
        }

        __syncthreads();
        if (s + 3 < G_NSTG) load_stage(s + 3, buf);
    }

    #pragma unroll
    for (int mt = 0; mt < 2; ++mt) {
        int row = mtile * G_TM + wm * 32 + mt * 16 + (lane >> 2);
        #pragma unroll
        for (int nt = 0; nt < 4; ++nt) {
            int col = ntile * G_TN + wn * 32 + nt * 8 + (lane & 3) * 2;
            float* d0 = g_C1 + ((size_t)chunk * NPOS + row) * NDIM + col;
            float* d1 = g_C1 + ((size_t)chunk * NPOS + row + 8) * NDIM + col;
            d0[0] = acc[mt][nt][0]; d0[1] = acc[mt][nt][1];
            d1[0] = acc[mt][nt][2]; d1[1] = acc[mt][nt][3];
        }
    }
}

// ---------------- squash 1: full SM coverage (288 CTAs x 64) -----------------
__global__ void k_squash1() {
    int t = blockIdx.x * 64 + threadIdx.x;   // (pos,f)
    if (t >= NPOS * FF) return;
    int pos = t >> 5;
    int f   = t & 31;
    float s[16];
    #pragma unroll
    for (int o = 0; o < 16; ++o) s[o] = 0.f;
    #pragma unroll
    for (int ch = 0; ch < G_KSPL; ++ch) {
        const float4* p = (const float4*)(g_C1 + ((size_t)ch * NPOS + pos) * NDIM + f * 16);
        #pragma unroll
        for (int q = 0; q < 4; ++q) {
            float4 v = p[q];
            s[q*4] += v.x; s[q*4+1] += v.y; s[q*4+2] += v.z; s[q*4+3] += v.w;
        }
    }
    float sn = 0.f;
    #pragma unroll
    for (int o = 0; o < 16; ++o) { s[o] *= (1.f / 32.f); sn += s[o] * s[o]; }
    float sc = (sn / (1.f + sn)) / sqrtf(sn + 1e-7f);
    float2* d = g_out1p + (size_t)t * 8;
    #pragma unroll
    for (int p = 0; p < 8; ++p) d[p] = make_float2(s[p] * sc, s[p + 8] * sc);
}

// ---------------- pass2 stage copy (16KB W tile) ------------------------------
__device__ __forceinline__ void stage_copy(u64* sdst, const float2* gsrc, int tid) {
    uint32_t s = (uint32_t)__cvta_generic_to_shared(sdst);
    const char* g = (const char*)gsrc;
    #pragma unroll
    for (int k = 0; k < 4; ++k) {
        int idx = tid + k * TPB;
        cp16(s + idx * 16, g + (size_t)idx * 16);
    }
    commit_cp();
}

// ---------------- pass 2: R7 champion config (unchanged) ----------------------
__global__ void __launch_bounds__(TPB, 1) k_pass2(const float* __restrict__ x) {
    extern __shared__ u64 sW[];   // 8 stages x 2048 u64
    int tid  = threadIdx.x;
    int lane = tid & 31;
    int w    = tid >> 5;
    int pos0 = blockIdx.x * POSB2 + w * 4;
    int cch  = blockIdx.y;
    int cbeg = cch * CPC2;
    const int NT = CPC2 / 4;   // 9 quartets

    const float* xb[4];
    #pragma unroll
    for (int q = 0; q < 4; ++q) xb[q] = x + pos_off(pos0 + q);

    u64 o1[4][8];
    #pragma unroll
    for (int q = 0; q < 4; ++q) {
        const u64* s = (const u64*)g_out1p + (((size_t)(pos0 + q) * FF) + lane) * 8;
        #pragma unroll
        for (int p = 0; p < 8; ++p) o1[q][p] = s[p];
    }

    u64 ce[4][8];
    #pragma unroll
    for (int q = 0; q < 4; ++q)
        #pragma unroll
        for (int p = 0; p < 8; ++p) ce[q][p] = 0ULL;

    #pragma unroll
    for (int j = 0; j < 4; ++j)
        stage_copy(sW + (size_t)j * 2048, g_Wtp + (size_t)(cbeg + j) * 2048, tid);
    #pragma unroll
    for (int j = 0; j < 4; ++j)
        stage_copy(sW + (size_t)(4 + j) * 2048, g_Wtp + (size_t)(cbeg + 4 + j) * 2048, tid);

    for (int t = 0; t < NT; ++t) {
        if (t + 1 < NT) wait_cp<4>(); else wait_cp<0>();
        __syncthreads();
        int sset = (t & 1) * 4;
        int qbeg = cbeg + t * 4;

        #pragma unroll
        for (int k = 0; k < 4; ++k) {
            int j = (w + k) & 3;
            int c = qbeg + j;
            int off = c_koff[c >> 5] + (c & 31) * DIN;
            float xs[4][8];
            #pragma unroll
            for (int q = 0; q < 4; ++q) {
                float4 v0 = ((const float4*)(xb[q] + off))[0];
                float4 v1 = ((const float4*)(xb[q] + off))[1];
                xs[q][0]=v0.x; xs[q][1]=v0.y; xs[q][2]=v0.z; xs[q][3]=v0.w;
                xs[q][4]=v1.x; xs[q][5]=v1.y; xs[q][6]=v1.z; xs[q][7]=v1.w;
            }

            u64 pr[4][8];
            #pragma unroll
            for (int q = 0; q < 4; ++q)
                #pragma unroll
                for (int p = 0; p < 8; ++p) pr[q][p] = 0ULL;

            const u64* wb = sW + (size_t)(sset + j) * 2048;
            #pragma unroll
            for (int i = 0; i < 8; ++i) {
                u64 xd0 = pk(xs[0][i], xs[0][i]);
                u64 xd1 = pk(xs[1][i], xs[1][i]);
                u64 xd2 = pk(xs[2][i], xs[2][i]);
                u64 xd3 = pk(xs[3][i], xs[3][i]);
                #pragma unroll
                for (int p = 0; p < 8; ++p) {
                    u64 wv = wb[(i * 8 + p) * 32 + lane];
                    pr[0][p] = fma2(wv, xd0, pr[0][p]);
                    pr[1][p] = fma2(wv, xd1, pr[1][p]);
                    pr[2][p] = fma2(wv, xd2, pr[2][p]);
                    pr[3][p] = fma2(wv, xd3, pr[3][p]);
                }
            }

            float e[4];
            #pragma unroll
            for (int q = 0; q < 4; ++q) {
                u64 a = 0ULL;
                #pragma unroll
                for (int p = 0; p < 8; ++p) a = fma2(pr[q][p], o1[q][p], a);
                float l, h;
                upk(a, l, h);
                e[q] = __expf(l + h);   // no max-subtraction: |agreement| is O(1)
            }

            float s0 = e[0], s1 = e[1], s2 = e[2], s3 = e[3];
            #pragma unroll
            for (int d = 16; d > 0; d >>= 1) {
                s0 += __shfl_xor_sync(0xffffffffu, s0, d);
                s1 += __shfl_xor_sync(0xffffffffu, s1, d);
                s2 += __shfl_xor_sync(0xffffffffu, s2, d);
                s3 += __shfl_xor_sync(0xffffffffu, s3, d);
            }
            float cc[4] = { __fdividef(e[0], s0), __fdividef(e[1], s1),
                            __fdividef(e[2], s2), __fdividef(e[3], s3) };

            #pragma unroll
            for (int q = 0; q < 4; ++q) {
                u64 cd = pk(cc[q], cc[q]);
                #pragma unroll
                for (int p = 0; p < 8; ++p)
                    ce[q][p] = fma2(pr[q][p], cd, ce[q][p]);
            }
        }

        __syncthreads();
        if (t + 2 < NT) {
            #pragma unroll
            for (int j = 0; j < 4; ++j)
                stage_copy(sW + (size_t)(sset + j) * 2048,
                           g_Wtp + (size_t)(cbeg + (t + 2) * 4 + j) * 2048, tid);
        }
    }

    #pragma unroll
    for (int q = 0; q < 4; ++q) {
        u64* d = (u64*)g_centp + (((size_t)cch * NPOS + pos0 + q) * FF + lane) * 8;
        #pragma unroll
        for (int p = 0; p < 8; ++p) d[p] = ce[q][p];
    }
}

// ---------------- squash 2: full SM coverage (288 CTAs x 64) -----------------
__global__ void k_squash2(float* __restrict__ out) {
    int t = blockIdx.x * 64 + threadIdx.x;   // (pos,f)
    if (t >= NPOS * FF) return;
    float sx[8], sy[8];
    #pragma unroll
    for (int p = 0; p < 8; ++p) { sx[p] = 0.f; sy[p] = 0.f; }
    #pragma unroll
    for (int ch = 0; ch < NCH2; ++ch) {
        const float2* s = g_centp + ((size_t)ch * NPOS * FF + t) * 8;
        #pragma unroll
        for (int p = 0; p < 8; ++p) { float2 v = s[p]; sx[p] += v.x; sy[p] += v.y; }
    }
    float sn = 0.f;
    #pragma unroll
    for (int p = 0; p < 8; ++p) sn += sx[p] * sx[p] + sy[p] * sy[p];
    float sc = (sn / (1.f + sn)) / sqrtf(sn + 1e-7f);
    float* d = out + (size_t)t * DOUT;
    #pragma unroll
    for (int p = 0; p < 8; ++p) { d[p] = sx[p] * sc; d[p + 8] = sy[p] * sc; }
}

// -----------------------------------------------------------------------------
extern "C" void kernel_launch(void* const* d_in, const int* in_sizes, int n_in,
                              void* d_out, int out_size) {
    const float* x = (const float*)d_in[0];
    const float* W = (const float*)d_in[1];
    if (n_in >= 2 && in_sizes[0] == (int)((size_t)FF * CCAP * DOUT * DIN)) {
        const float* t = x; x = W; W = t;
    }
    float* out = (float*)d_out;

    cudaFuncSetAttribute(k_pass1mma, cudaFuncAttributeMaxDynamicSharedMemorySize, SMEM_G);
    cudaFuncSetAttribute(k_pass2, cudaFuncAttributeMaxDynamicSharedMemorySize, SMEM_BYTES);

    k_prep<<<CCAP, 256>>>(W);
    k_pass1mma<<<dim3(NPOS / G_TM, NDIM / G_TN, G_KSPL), G_TPB, SMEM_G>>>(x);
    k_squash1<<<(NPOS * FF + 63) / 64, 64>>>();
    k_pass2<<<dim3(NPB2, NCH2), TPB, SMEM_BYTES>>>(x);
    k_squash2<<<(NPOS * FF + 63) / 64, 64>>>(out);
}